// round 9
// baseline (speedup 1.0000x reference)
#include <cuda_runtime.h>

// Problem constants
#define HH    224
#define WW    224
#define CC    3
#define SS    17
#define NN    32
#define TILE  32
#define NTX   7            // 224/32
#define RW    46           // fixed region side: 31*(cos30+sin30)=42.35, +2 taps +margin
#define PLANE (HH*WW)      // 50176

__global__ __launch_bounds__(256, 6)
void rot_bilinear_kernel(const float* __restrict__ x,
                         const float* __restrict__ thetas,
                         float* __restrict__ out)
{
    // Channel-interleaved region: sm[y*RW + x] = {ch0, ch1, ch2, 0}
    __shared__ float4 sm[RW * RW];   // 2116 * 16B = 33856 B

    const int tile  = blockIdx.x;           // 0..48
    const int s_idx = blockIdx.y;           // 0..16
    const int n     = blockIdx.z;           // 0..31
    const int th0   = (tile / NTX) * TILE;
    const int tw0   = (tile % NTX) * TILE;
    const int tid   = threadIdx.x;

    const float theta = __ldg(&thetas[n * SS + s_idx]);
    float st, ct;
    sincosf(theta, &st, &ct);

    // Input-pixel coords of output (w,h):
    //   ix = ct*(w-111.5) - st*(h-111.5) + 111.5
    //   iy = st*(w-111.5) + ct*(h-111.5) + 111.5
    // (algebraically identical to the reference's normalized grid.)
    const float Xlo = (float)tw0 - 111.5f, Xhi = Xlo + (float)(TILE - 1);
    const float Ylo = (float)th0 - 111.5f, Yhi = Ylo + (float)(TILE - 1);

    // Separable bbox of the linear map over the tile.
    const float ctXl = ct * Xlo, ctXh = ct * Xhi;
    const float stYl = st * Ylo, stYh = st * Yhi;
    const float stXl = st * Xlo, stXh = st * Xhi;
    const float ctYl = ct * Ylo, ctYh = ct * Yhi;
    const float ixmin = fminf(ctXl, ctXh) - fmaxf(stYl, stYh) + 111.5f;
    const float iymin = fminf(stXl, stXh) + fminf(ctYl, ctYh) + 111.5f;

    // Region origin (0.01 slack covers fma-vs-mul/add rounding differences).
    const int x0u = (int)floorf(ixmin - 0.01f);
    const int y0u = (int)floorf(iymin - 0.01f);

    // ---- Cooperative load of the fixed RW x RW region, zero-padded ----
    {
        const float* img = x + (size_t)n * (CC * PLANE);
        #pragma unroll 3
        for (int i = tid; i < RW * RW; i += 256) {
            const int r  = i / RW;          // compile-time divisor -> mul+shift
            const int c  = i - r * RW;
            const int gy = y0u + r;
            const int gx = x0u + c;
            const float ok = ((unsigned)gy < (unsigned)HH &&
                              (unsigned)gx < (unsigned)WW) ? 1.0f : 0.0f;
            const int cg = min(max(gy, 0), HH - 1) * WW + min(max(gx, 0), WW - 1);
            float4 v;
            v.x = img[cg]             * ok;
            v.y = img[PLANE + cg]     * ok;
            v.z = img[2 * PLANE + cg] * ok;
            v.w = 0.0f;
            sm[i] = v;
        }
    }
    __syncthreads();

    // ---- Each thread: 4 consecutive-w pixels; float4 stores per channel ----
    const int hh = tid >> 3;                // 0..31
    const int ww = (tid & 7) << 2;          // 0,4,...,28

    const float Yf = (float)(th0 + hh) - 111.5f;
    const float bx = fmaf(-st, Yf, 111.5f); // ix = ct*Xf + bx
    const float by = fmaf( ct, Yf, 111.5f); // iy = st*Xf + by

    float r0[4], r1[4], r2[4];

    #pragma unroll
    for (int j = 0; j < 4; j++) {
        const float Xf = (float)(tw0 + ww + j) - 111.5f;
        const float ix = fmaf(ct, Xf, bx);
        const float iy = fmaf(st, Xf, by);

        const float fx0 = floorf(ix);
        const float fy0 = floorf(iy);
        const float wx1 = ix - fx0;
        const float wy1 = iy - fy0;
        const float wx0 = 1.0f - wx1;
        const float wy0 = 1.0f - wy1;

        // Region-relative tap base; taps guaranteed inside the RW x RW region,
        // zero padding supplies the out-of-image value.
        const int sx = (int)fx0 - x0u;
        const int sy = (int)fy0 - y0u;
        const float4* t = &sm[sy * RW + sx];
        const float4 t00 = t[0];
        const float4 t01 = t[1];
        const float4 t10 = t[RW];
        const float4 t11 = t[RW + 1];

        const float w00 = wy0 * wx0;
        const float w01 = wy0 * wx1;
        const float w10 = wy1 * wx0;
        const float w11 = wy1 * wx1;

        r0[j] = fmaf(w11, t11.x, fmaf(w10, t10.x, fmaf(w01, t01.x, w00 * t00.x)));
        r1[j] = fmaf(w11, t11.y, fmaf(w10, t10.y, fmaf(w01, t01.y, w00 * t00.y)));
        r2[j] = fmaf(w11, t11.z, fmaf(w10, t10.z, fmaf(w01, t01.z, w00 * t00.z)));
    }

    float* outp = out + ((size_t)(n * SS + s_idx) * CC) * PLANE
                      + (th0 + hh) * WW + tw0 + ww;
    *(float4*)(outp)             = make_float4(r0[0], r0[1], r0[2], r0[3]);
    *(float4*)(outp + PLANE)     = make_float4(r1[0], r1[1], r1[2], r1[3]);
    *(float4*)(outp + 2 * PLANE) = make_float4(r2[0], r2[1], r2[2], r2[3]);
}

extern "C" void kernel_launch(void* const* d_in, const int* in_sizes, int n_in,
                              void* d_out, int out_size)
{
    const float* x      = (const float*)d_in[0];   // (32,3,224,224)
    const float* thetas = (const float*)d_in[1];   // (32,17)
    float* out          = (float*)d_out;           // (32,17,3,224,224)

    dim3 grid(NTX * NTX, SS, NN);  // (49, 17, 32)
    rot_bilinear_kernel<<<grid, 256>>>(x, thetas, out);
}

// round 12
// speedup vs baseline: 1.9254x; 1.9254x over previous
#include <cuda_runtime.h>

// Problem constants
#define HH    224
#define WW    224
#define CC    3
#define SS    17
#define NN    32
#define TILE  32
#define NTX   7            // 224/32
#define RW    46           // fixed region side: 31*(cos30+sin30)=42.4, +taps +margin
#define SMP   47           // padded row stride (floats) -> conflict-free
#define P1    (RW*SMP)     // channel plane stride in smem floats = 2162
#define PLANE (HH*WW)      // 50176

__global__ __launch_bounds__(256)
void rot_bilinear_kernel(const float* __restrict__ x,
                         const float* __restrict__ thetas,
                         float* __restrict__ out)
{
    __shared__ float sm[CC][RW][SMP];   // 3*46*47*4 = 25944 B

    const int tile  = blockIdx.x;           // 0..48
    const int s_idx = blockIdx.y;           // 0..16
    const int n     = blockIdx.z;           // 0..31
    const int th0   = (tile / NTX) * TILE;
    const int tw0   = (tile % NTX) * TILE;
    const int tid   = threadIdx.x;

    const float theta = __ldg(&thetas[n * SS + s_idx]);
    float st, ct;
    sincosf(theta, &st, &ct);

    // Input-pixel coords of output (w,h):
    //   ix = ct*(w-111.5) - st*(h-111.5) + 111.5
    //   iy = st*(w-111.5) + ct*(h-111.5) + 111.5
    const float Xlo = (float)tw0 - 111.5f, Xhi = Xlo + (float)(TILE - 1);
    const float Ylo = (float)th0 - 111.5f, Yhi = Ylo + (float)(TILE - 1);

    // Separable bbox minimum of the linear map over the tile.
    const float ixmin = fminf(ct * Xlo, ct * Xhi)
                      - fmaxf(st * Ylo, st * Yhi) + 111.5f;
    const float iymin = fminf(st * Xlo, st * Xhi)
                      + fminf(ct * Ylo, ct * Yhi) + 111.5f;

    // Region origin (0.01 slack covers fma/rounding differences).
    const int x0u = (int)floorf(ixmin - 0.01f);
    const int y0u = (int)floorf(iymin - 0.01f);

    // ---- Cooperative load: fixed RW x RW region, 3 planes, zero-padded ----
    {
        const float* img = x + (size_t)n * (CC * PLANE);
        for (int i = tid; i < RW * RW; i += 256) {
            const int r  = i / RW;             // compile-time divisor
            const int c  = i - r * RW;
            const int gy = y0u + r;
            const int gx = x0u + c;
            const float ok = ((unsigned)gy < (unsigned)HH &&
                              (unsigned)gx < (unsigned)WW) ? 1.0f : 0.0f;
            const int cg = min(max(gy, 0), HH - 1) * WW + min(max(gx, 0), WW - 1);
            sm[0][r][c] = img[cg]             * ok;
            sm[1][r][c] = img[cg + PLANE]     * ok;
            sm[2][r][c] = img[cg + 2 * PLANE] * ok;
        }
    }
    __syncthreads();

    // ---- Hot loop: warp = one row of 32 consecutive columns; 4 rows/thread ----
    const int lane = tid & 31;
    const int wrp  = tid >> 5;                  // 0..7

    const float Xf  = (float)(tw0 + lane) - 111.5f;
    const float ctX = ct * Xf;                  // row-invariant parts
    const float stX = st * Xf;

    float* outp = out + ((size_t)(n * SS + s_idx) * CC) * PLANE
                      + (th0 + wrp) * WW + (tw0 + lane);

    #pragma unroll
    for (int j = 0; j < 4; j++) {
        const float Yf = (float)(th0 + wrp + 8 * j) - 111.5f;
        const float ix = fmaf(-st, Yf, ctX) + 111.5f;
        const float iy = fmaf( ct, Yf, stX) + 111.5f;

        const float fx0 = floorf(ix);
        const float fy0 = floorf(iy);
        const float wx1 = ix - fx0;
        const float wy1 = iy - fy0;
        const float wx0 = 1.0f - wx1;
        const float wy0 = 1.0f - wy1;

        const int sx = (int)fx0 - x0u;          // in [0, RW-2] by construction
        const int sy = (int)fy0 - y0u;

        const float w00 = wy0 * wx0;
        const float w01 = wy0 * wx1;
        const float w10 = wy1 * wx0;
        const float w11 = wy1 * wx1;

        // Single base pointer; all 12 taps via compile-time immediates.
        const float* t = &sm[0][sy][sx];

        const float v0 = fmaf(w11, t[SMP + 1],
                         fmaf(w10, t[SMP],
                         fmaf(w01, t[1], w00 * t[0])));
        const float v1 = fmaf(w11, t[P1 + SMP + 1],
                         fmaf(w10, t[P1 + SMP],
                         fmaf(w01, t[P1 + 1], w00 * t[P1])));
        const float v2 = fmaf(w11, t[2 * P1 + SMP + 1],
                         fmaf(w10, t[2 * P1 + SMP],
                         fmaf(w01, t[2 * P1 + 1], w00 * t[2 * P1])));

        // Single base pointer; all 3 stores via compile-time immediates.
        outp[j * 8 * WW]             = v0;
        outp[j * 8 * WW + PLANE]     = v1;
        outp[j * 8 * WW + 2 * PLANE] = v2;
    }
}

extern "C" void kernel_launch(void* const* d_in, const int* in_sizes, int n_in,
                              void* d_out, int out_size)
{
    const float* x      = (const float*)d_in[0];   // (32,3,224,224)
    const float* thetas = (const float*)d_in[1];   // (32,17)
    float* out          = (float*)d_out;           // (32,17,3,224,224)

    dim3 grid(NTX * NTX, SS, NN);  // (49, 17, 32)
    rot_bilinear_kernel<<<grid, 256>>>(x, thetas, out);
}